// round 5
// baseline (speedup 1.0000x reference)
#include <cuda_runtime.h>

#define DIN     4096
#define DOUT    4096
#define RNK     16
#define NROWS   8192            // 4*2048

// ---------------- K1 geometry ----------------
#define K1_THREADS 128
#define K1_RPW     8            // rows per warp
#define K1_ROWS    32           // rows per block
#define KSPLIT     2
#define KHALF      (DIN / KSPLIT)        // 2048
#define K1_KT      128                   // A tile k-extent
#define K1_NST     3
#define K1_TILES   (KHALF / K1_KT)       // 16
#define K1_NB      (KHALF / 16)          // 128 batches of 16 k
#define AP         260                   // A rank-pair row pitch (== 4 mod 32)
#define K1_GRID    (NROWS / K1_ROWS * KSPLIT)   // 512

// ---------------- K2 geometry ----------------
#define K2_THREADS 128
#define K2_ROWS    16
#define K2_GRID    (NROWS / K2_ROWS)     // 512

// t scratch: [row][split][rank] floats = 1 MB
__device__ float g_t[NROWS * KSPLIT * RNK];

__device__ __forceinline__ unsigned long long pk2(float v) {
    unsigned long long r;
    asm("mov.b64 %0, {%1, %1};" : "=l"(r) : "f"(v));
    return r;
}
__device__ __forceinline__ void ffma2(unsigned long long &acc,
                                      unsigned long long a, unsigned long long b) {
    asm("fma.rn.f32x2 %0, %1, %2, %0;" : "+l"(acc) : "l"(a), "l"(b));
}
__device__ __forceinline__ unsigned long long add2(unsigned long long a,
                                                   unsigned long long b) {
    unsigned long long d;
    asm("add.rn.f32x2 %0, %1, %2;" : "=l"(d) : "l"(a), "l"(b));
    return d;
}
__device__ __forceinline__ unsigned su32(const void* p) {
    unsigned a;
    asm("{ .reg .u64 t; cvta.to.shared.u64 t, %1; cvt.u32.u64 %0, t; }"
        : "=r"(a) : "l"(p));
    return a;
}
__device__ __forceinline__ void cpa8(unsigned d, const void* s) {
    asm volatile("cp.async.ca.shared.global [%0], [%1], 8;" :: "r"(d), "l"(s));
}

// ================= K1: t_partial = x @ A  (split-K) =================
__global__ void __launch_bounds__(K1_THREADS, 4)
lora_k1(const float* __restrict__ x, const float* __restrict__ A)
{
    __shared__ float As2[K1_NST * 8 * AP];   // ~25 KB: A tiles, rank-pair major

    const int tid  = threadIdx.x;
    const int lane = tid & 31;
    const int warp = tid >> 5;
    const int rp   = lane >> 2;              // rank-pair 0..7
    const int ksub = lane & 3;               // k-quarter within a 16-k batch
    const int rb    = blockIdx.x >> 1;
    const int split = blockIdx.x & 1;
    const int k0    = split * KHALF;
    const long long rowBase = (long long)rb * K1_ROWS + warp * K1_RPW;
    const unsigned  smb = su32(As2);

    // A tile cp.async issue (rank-pair major, 8B granules)
    auto issueA = [&](int tile, int stg) {
        const float* Ag = A + (long long)(k0 + tile * K1_KT) * RNK;
        const unsigned as = smb + (unsigned)(stg * 8 * AP) * 4u;
        #pragma unroll
        for (int m = 0; m < 8; m++) {
            int g = tid + m * K1_THREADS;    // 1024 granules: k(128) x rp(8)
            int k = g >> 3, r8 = g & 7;
            cpa8(as + (unsigned)(r8 * AP + 2 * k) * 4u, Ag + k * RNK + 2 * r8);
        }
    };

    issueA(0, 0); asm volatile("cp.async.commit_group;");
    issueA(1, 1); asm volatile("cp.async.commit_group;");

    unsigned long long acc[K1_RPW];
    #pragma unroll
    for (int r = 0; r < K1_RPW; r++) acc[r] = 0ULL;

    const float* xw = x + rowBase * DIN + k0 + 4 * ksub;

    // preload x batch 0 (each lane: 16B per row, duplicated across rp lanes)
    float4 xv[K1_RPW];
    #pragma unroll
    for (int r = 0; r < K1_RPW; r++)
        xv[r] = *reinterpret_cast<const float4*>(xw + (long long)r * DIN);

    #pragma unroll 1
    for (int t = 0; t < K1_TILES; t++) {
        asm volatile("cp.async.wait_group %0;" :: "n"(1));
        __syncthreads();

        const float* as = As2 + (t % K1_NST) * 8 * AP + rp * AP + 8 * ksub;

        #pragma unroll
        for (int b = 0; b < K1_KT / 16; b++) {
            const int gb = t * (K1_KT / 16) + b;
            // A fragment: ranks(2rp,2rp+1) for this lane's 4 k
            ulonglong2 fa = *reinterpret_cast<const ulonglong2*>(as + 32 * b);
            ulonglong2 fb = *reinterpret_cast<const ulonglong2*>(as + 32 * b + 4);

            // prefetch next batch's x (clamped on last batch; wasted once)
            const int nk = (gb + 1 < K1_NB) ? (gb + 1) * 16 : 0;
            float4 xn[K1_RPW];
            #pragma unroll
            for (int r = 0; r < K1_RPW; r++)
                xn[r] = *reinterpret_cast<const float4*>(
                            xw + (long long)r * DIN + nk);

            #pragma unroll
            for (int r = 0; r < K1_RPW; r++) {
                ffma2(acc[r], pk2(xv[r].x), fa.x);
                ffma2(acc[r], pk2(xv[r].y), fa.y);
                ffma2(acc[r], pk2(xv[r].z), fb.x);
                ffma2(acc[r], pk2(xv[r].w), fb.y);
            }
            #pragma unroll
            for (int r = 0; r < K1_RPW; r++) xv[r] = xn[r];
        }

        if (t + 2 < K1_TILES) issueA(t + 2, (t + 2) % K1_NST);
        asm volatile("cp.async.commit_group;");
    }

    // reduce over the 4 k-quarters within each quad
    #pragma unroll
    for (int r = 0; r < K1_RPW; r++) {
        acc[r] = add2(acc[r], __shfl_xor_sync(0xffffffffu, acc[r], 1));
        acc[r] = add2(acc[r], __shfl_xor_sync(0xffffffffu, acc[r], 2));
    }
    if (ksub == 0) {
        #pragma unroll
        for (int r = 0; r < K1_RPW; r++) {
            long long idx = (rowBase + r) * (KSPLIT * RNK) + split * RNK + 2 * rp;
            *reinterpret_cast<unsigned long long*>(&g_t[idx]) = acc[r];
        }
    }
}

// ================= K2: out = (t0 + t1) @ B =================
__global__ void __launch_bounds__(K2_THREADS, 4)
lora_k2(const float* __restrict__ B, float* __restrict__ out)
{
    __shared__ unsigned long long ts2[K2_ROWS][RNK];   // t, packed-dup f32x2

    const int tid = threadIdx.x;
    const long long rowBase = (long long)blockIdx.x * K2_ROWS;

    // load t (both splits), combine, pack duplicated
    {
        const int row = tid >> 3, j = tid & 7;          // 16 rows x 8 f2-granules
        const float* tp = &g_t[(rowBase + row) * (KSPLIT * RNK) + 2 * j];
        float2 a = *reinterpret_cast<const float2*>(tp);
        float2 b = *reinterpret_cast<const float2*>(tp + RNK);
        ts2[row][2 * j]     = pk2(a.x + b.x);
        ts2[row][2 * j + 1] = pk2(a.y + b.y);
    }
    __syncthreads();

    // 8 passes of 512 cols; thread owns 4 cols; B reg-cached, reused 16 rows
    #pragma unroll 1
    for (int p = 0; p < 8; p++) {
        const int j = p * 512 + tid * 4;
        ulonglong2 Breg[RNK];
        #pragma unroll
        for (int r = 0; r < RNK; r++)
            Breg[r] = *reinterpret_cast<const ulonglong2*>(B + (long long)r * DOUT + j);

        #pragma unroll 2
        for (int row = 0; row < K2_ROWS; row++) {
            const ulonglong2* tr = reinterpret_cast<const ulonglong2*>(ts2[row]);
            unsigned long long accLo = 0ULL, accHi = 0ULL;
            #pragma unroll
            for (int rr = 0; rr < RNK / 2; rr++) {
                ulonglong2 tp2 = tr[rr];                 // broadcast LDS.128
                ffma2(accLo, tp2.x, Breg[2 * rr].x);
                ffma2(accHi, tp2.x, Breg[2 * rr].y);
                ffma2(accLo, tp2.y, Breg[2 * rr + 1].x);
                ffma2(accHi, tp2.y, Breg[2 * rr + 1].y);
            }
            ulonglong2 o; o.x = accLo; o.y = accHi;
            *reinterpret_cast<ulonglong2*>(
                out + (rowBase + row) * (long long)DOUT + j) = o;
        }
    }
}

extern "C" void kernel_launch(void* const* d_in, const int* in_sizes, int n_in,
                              void* d_out, int out_size) {
    const float* x = (const float*)d_in[0];   // [4, 2048, 4096]
    const float* A = (const float*)d_in[1];   // [4096, 16]
    const float* B = (const float*)d_in[2];   // [16, 4096]
    float* out = (float*)d_out;               // [4, 2048, 4096]

    lora_k1<<<K1_GRID, K1_THREADS>>>(x, A);
    lora_k2<<<K2_GRID, K2_THREADS>>>(B, out);
}

// round 6
// speedup vs baseline: 1.0792x; 1.0792x over previous
#include <cuda_runtime.h>

#define DIN     4096
#define DOUT    4096
#define RNK     16
#define NROWS   8192            // 4*2048

// ---------------- K1 geometry ----------------
#define K1_THREADS 256
#define K1_WARPS   8
#define K1_RPW     4            // rows per warp
#define K1_ROWS    32           // rows per block
#define KSPLIT     2
#define KHALF      (DIN / KSPLIT)        // 2048
#define K1_KT      128                   // A tile k-extent
#define K1_NST     3
#define K1_TILES   (KHALF / K1_KT)       // 16
#define K1_NB      (KHALF / 16)          // 128 batches of 16 k
#define AP         260                   // A rank-pair row pitch (== 4 mod 32)
#define K1_GRID    (NROWS / K1_ROWS * KSPLIT)   // 512

// ---------------- K2 geometry ----------------
#define K2_THREADS 256
#define K2_ROWS    16
#define K2_GRID    (NROWS / K2_ROWS)     // 512

// t scratch: [row][split][rank] floats = 1 MB
__device__ float g_t[NROWS * KSPLIT * RNK];

__device__ __forceinline__ unsigned long long pk2(float v) {
    unsigned long long r;
    asm("mov.b64 %0, {%1, %1};" : "=l"(r) : "f"(v));
    return r;
}
__device__ __forceinline__ void ffma2(unsigned long long &acc,
                                      unsigned long long a, unsigned long long b) {
    asm("fma.rn.f32x2 %0, %1, %2, %0;" : "+l"(acc) : "l"(a), "l"(b));
}
__device__ __forceinline__ unsigned long long add2(unsigned long long a,
                                                   unsigned long long b) {
    unsigned long long d;
    asm("add.rn.f32x2 %0, %1, %2;" : "=l"(d) : "l"(a), "l"(b));
    return d;
}
__device__ __forceinline__ unsigned su32(const void* p) {
    unsigned a;
    asm("{ .reg .u64 t; cvta.to.shared.u64 t, %1; cvt.u32.u64 %0, t; }"
        : "=r"(a) : "l"(p));
    return a;
}
__device__ __forceinline__ void cpa8(unsigned d, const void* s) {
    asm volatile("cp.async.ca.shared.global [%0], [%1], 8;" :: "r"(d), "l"(s));
}

// ================= K1: t_partial = x @ A  (split-K) =================
__global__ void __launch_bounds__(K1_THREADS, 3)
lora_k1(const float* __restrict__ x, const float* __restrict__ A)
{
    __shared__ float As2[K1_NST * 8 * AP];   // ~25 KB: A tiles, rank-pair major

    const int tid  = threadIdx.x;
    const int lane = tid & 31;
    const int warp = tid >> 5;
    const int rp   = lane >> 2;              // rank-pair 0..7
    const int ksub = lane & 3;               // k-quarter within a 16-k batch
    const int rb    = blockIdx.x >> 1;
    const int split = blockIdx.x & 1;
    const int k0    = split * KHALF;
    const long long rowBase = (long long)rb * K1_ROWS + warp * K1_RPW;
    const unsigned  smb = su32(As2);

    // A tile cp.async issue (rank-pair major, 8B granules), 4 per thread
    auto issueA = [&](int tile, int stg) {
        const float* Ag = A + (long long)(k0 + tile * K1_KT) * RNK;
        const unsigned as = smb + (unsigned)(stg * 8 * AP) * 4u;
        #pragma unroll
        for (int m = 0; m < 4; m++) {
            int g = tid + m * K1_THREADS;    // 1024 granules: k(128) x rp(8)
            int k = g >> 3, r8 = g & 7;
            cpa8(as + (unsigned)(r8 * AP + 2 * k) * 4u, Ag + k * RNK + 2 * r8);
        }
    };

    issueA(0, 0); asm volatile("cp.async.commit_group;");
    issueA(1, 1); asm volatile("cp.async.commit_group;");

    unsigned long long acc[K1_RPW];
    #pragma unroll
    for (int r = 0; r < K1_RPW; r++) acc[r] = 0ULL;

    const float* xw = x + rowBase * DIN + k0 + 4 * ksub;

    // preload x batch 0
    float4 xv[K1_RPW];
    #pragma unroll
    for (int r = 0; r < K1_RPW; r++)
        xv[r] = *reinterpret_cast<const float4*>(xw + (long long)r * DIN);

    #pragma unroll 1
    for (int t = 0; t < K1_TILES; t++) {
        asm volatile("cp.async.wait_group %0;" :: "n"(1));
        __syncthreads();

        const float* as = As2 + (t % K1_NST) * 8 * AP + rp * AP + 8 * ksub;

        #pragma unroll
        for (int b = 0; b < K1_KT / 16; b++) {
            const int gb = t * (K1_KT / 16) + b;
            // A fragment: ranks(2rp,2rp+1) for this lane's 4 k
            ulonglong2 fa = *reinterpret_cast<const ulonglong2*>(as + 32 * b);
            ulonglong2 fb = *reinterpret_cast<const ulonglong2*>(as + 32 * b + 4);

            // prefetch next batch's x (clamped on last batch)
            const int nk = (gb + 1 < K1_NB) ? (gb + 1) * 16 : 0;
            float4 xn[K1_RPW];
            #pragma unroll
            for (int r = 0; r < K1_RPW; r++)
                xn[r] = *reinterpret_cast<const float4*>(
                            xw + (long long)r * DIN + nk);

            #pragma unroll
            for (int r = 0; r < K1_RPW; r++) {
                ffma2(acc[r], pk2(xv[r].x), fa.x);
                ffma2(acc[r], pk2(xv[r].y), fa.y);
                ffma2(acc[r], pk2(xv[r].z), fb.x);
                ffma2(acc[r], pk2(xv[r].w), fb.y);
            }
            #pragma unroll
            for (int r = 0; r < K1_RPW; r++) xv[r] = xn[r];
        }

        if (t + 2 < K1_TILES) issueA(t + 2, (t + 2) % K1_NST);
        asm volatile("cp.async.commit_group;");
    }

    // reduce over the 4 k-quarters within each quad
    #pragma unroll
    for (int r = 0; r < K1_RPW; r++) {
        acc[r] = add2(acc[r], __shfl_xor_sync(0xffffffffu, acc[r], 1));
        acc[r] = add2(acc[r], __shfl_xor_sync(0xffffffffu, acc[r], 2));
    }
    if (ksub == 0) {
        #pragma unroll
        for (int r = 0; r < K1_RPW; r++) {
            long long idx = (rowBase + r) * (KSPLIT * RNK) + split * RNK + 2 * rp;
            *reinterpret_cast<unsigned long long*>(&g_t[idx]) = acc[r];
        }
    }
}

// ================= K2: out = (t0 + t1) @ B =================
__global__ void __launch_bounds__(K2_THREADS, 2)
lora_k2(const float* __restrict__ B, float* __restrict__ out)
{
    __shared__ unsigned long long ts2[K2_ROWS][RNK];   // t, packed-dup f32x2

    const int tid = threadIdx.x;
    const long long rowBase = (long long)blockIdx.x * K2_ROWS;

    // load t (both splits), combine, pack duplicated (first 128 threads)
    if (tid < 128) {
        const int row = tid >> 3, j = tid & 7;          // 16 rows x 8 f2-granules
        const float* tp = &g_t[(rowBase + row) * (KSPLIT * RNK) + 2 * j];
        float2 a = *reinterpret_cast<const float2*>(tp);
        float2 b = *reinterpret_cast<const float2*>(tp + RNK);
        ts2[row][2 * j]     = pk2(a.x + b.x);
        ts2[row][2 * j + 1] = pk2(a.y + b.y);
    }
    __syncthreads();

    // 4 passes of 1024 cols; thread owns 4 cols; B reg-cached, reused 16 rows
    #pragma unroll 1
    for (int p = 0; p < 4; p++) {
        const int j = p * 1024 + tid * 4;
        ulonglong2 Breg[RNK];
        #pragma unroll
        for (int r = 0; r < RNK; r++)
            Breg[r] = *reinterpret_cast<const ulonglong2*>(B + (long long)r * DOUT + j);

        #pragma unroll 2
        for (int row = 0; row < K2_ROWS; row++) {
            const ulonglong2* tr = reinterpret_cast<const ulonglong2*>(ts2[row]);
            unsigned long long accLo = 0ULL, accHi = 0ULL;
            #pragma unroll
            for (int rr = 0; rr < RNK / 2; rr++) {
                ulonglong2 tp2 = tr[rr];                 // broadcast LDS.128
                ffma2(accLo, tp2.x, Breg[2 * rr].x);
                ffma2(accHi, tp2.x, Breg[2 * rr].y);
                ffma2(accLo, tp2.y, Breg[2 * rr + 1].x);
                ffma2(accHi, tp2.y, Breg[2 * rr + 1].y);
            }
            ulonglong2 o; o.x = accLo; o.y = accHi;
            *reinterpret_cast<ulonglong2*>(
                out + (rowBase + row) * (long long)DOUT + j) = o;
        }
    }
}

extern "C" void kernel_launch(void* const* d_in, const int* in_sizes, int n_in,
                              void* d_out, int out_size) {
    const float* x = (const float*)d_in[0];   // [4, 2048, 4096]
    const float* A = (const float*)d_in[1];   // [4096, 16]
    const float* B = (const float*)d_in[2];   // [16, 4096]
    float* out = (float*)d_out;               // [4, 2048, 4096]

    lora_k1<<<K1_GRID, K1_THREADS>>>(x, A);
    lora_k2<<<K2_GRID, K2_THREADS>>>(B, out);
}

// round 7
// speedup vs baseline: 1.5371x; 1.4242x over previous
#include <cuda_runtime.h>

#define DIN     4096
#define DOUT    4096
#define RNK     16
#define NROWS   8192            // 4*2048

// ---------------- K1 geometry ----------------
#define K1_THREADS 128
#define K1_RPW     8            // rows per warp
#define K1_ROWS    32           // rows per block (4 warps x 8)
#define KSPLIT     2
#define KHALF      (DIN / KSPLIT)        // 2048
#define K1_KT      128                   // A tile k-extent
#define K1_NST     3
#define K1_TILES   (KHALF / K1_KT)       // 16
#define K1_NB      (KHALF / 16)          // 128 batches of 16 k
#define AP         260                   // A rank-pair row pitch (== 4 mod 32)
#define K1_GRID    (NROWS / K1_ROWS * KSPLIT)   // 512

// ---------------- K2 geometry ----------------
#define K2_THREADS 256
#define K2_ROWS    16
#define K2_GRID    (NROWS / K2_ROWS)     // 512

// t scratch: [row][split][rank] floats = 1 MB
__device__ float g_t[NROWS * KSPLIT * RNK];

__device__ __forceinline__ unsigned long long pk2(float v) {
    unsigned long long r;
    asm("mov.b64 %0, {%1, %1};" : "=l"(r) : "f"(v));
    return r;
}
__device__ __forceinline__ void ffma2(unsigned long long &acc,
                                      unsigned long long a, unsigned long long b) {
    asm("fma.rn.f32x2 %0, %1, %2, %0;" : "+l"(acc) : "l"(a), "l"(b));
}
__device__ __forceinline__ unsigned long long add2(unsigned long long a,
                                                   unsigned long long b) {
    unsigned long long d;
    asm("add.rn.f32x2 %0, %1, %2;" : "=l"(d) : "l"(a), "l"(b));
    return d;
}
__device__ __forceinline__ unsigned su32(const void* p) {
    unsigned a;
    asm("{ .reg .u64 t; cvta.to.shared.u64 t, %1; cvt.u32.u64 %0, t; }"
        : "=r"(a) : "l"(p));
    return a;
}
__device__ __forceinline__ void cpa8(unsigned d, const void* s) {
    asm volatile("cp.async.ca.shared.global [%0], [%1], 8;" :: "r"(d), "l"(s));
}

// ================= K1: t_partial = x @ A  (split-K) =================
__global__ void __launch_bounds__(K1_THREADS, 4)
lora_k1(const float* __restrict__ x, const float* __restrict__ A)
{
    __shared__ float As2[K1_NST * 8 * AP];   // ~25 KB: A tiles, rank-pair major

    const int tid  = threadIdx.x;
    const int lane = tid & 31;
    const int warp = tid >> 5;
    const int rp   = lane >> 2;              // rank-pair 0..7
    const int ksub = lane & 3;               // k-quarter within a 16-k batch
    const int rb    = blockIdx.x >> 1;
    const int split = blockIdx.x & 1;
    const int k0    = split * KHALF;
    const long long rowBase = (long long)rb * K1_ROWS + warp * K1_RPW;
    const unsigned  smb = su32(As2);

    // A tile cp.async issue (rank-pair major, 8B granules), 8 per thread
    auto issueA = [&](int tile, int stg) {
        const float* Ag = A + (long long)(k0 + tile * K1_KT) * RNK;
        const unsigned as = smb + (unsigned)(stg * 8 * AP) * 4u;
        #pragma unroll
        for (int m = 0; m < 8; m++) {
            int g = tid + m * K1_THREADS;    // 1024 granules: k(128) x rp(8)
            int k = g >> 3, r8 = g & 7;
            cpa8(as + (unsigned)(r8 * AP + 2 * k) * 4u, Ag + k * RNK + 2 * r8);
        }
    };

    issueA(0, 0); asm volatile("cp.async.commit_group;");
    issueA(1, 1); asm volatile("cp.async.commit_group;");

    unsigned long long acc[K1_RPW];
    #pragma unroll
    for (int r = 0; r < K1_RPW; r++) acc[r] = 0ULL;

    const float* xw = x + rowBase * DIN + k0 + 4 * ksub;

    // distance-2 x prefetch: two register sets, 2 batches in flight
    float4 xa[K1_RPW], xb[K1_RPW];
    #pragma unroll
    for (int r = 0; r < K1_RPW; r++) {
        xa[r] = *reinterpret_cast<const float4*>(xw + (long long)r * DIN);
        xb[r] = *reinterpret_cast<const float4*>(xw + (long long)r * DIN + 16);
    }

    #pragma unroll 1
    for (int t = 0; t < K1_TILES; t++) {
        asm volatile("cp.async.wait_group %0;" :: "n"(1));
        __syncthreads();

        const float* asl = As2 + (t % K1_NST) * 8 * AP + rp * AP + 8 * ksub;

        #pragma unroll
        for (int j = 0; j < 4; j++) {            // 4 double-batches per tile
            const int g = t * 8 + 2 * j;

            // ---- batch g (xa), A frag at bt = 2j ----
            {
                ulonglong2 fa = *reinterpret_cast<const ulonglong2*>(asl + 32 * (2 * j));
                ulonglong2 fb = *reinterpret_cast<const ulonglong2*>(asl + 32 * (2 * j) + 4);
                #pragma unroll
                for (int r = 0; r < K1_RPW; r++) {
                    ffma2(acc[r], pk2(xa[r].x), fa.x);
                    ffma2(acc[r], pk2(xa[r].y), fa.y);
                    ffma2(acc[r], pk2(xa[r].z), fb.x);
                    ffma2(acc[r], pk2(xa[r].w), fb.y);
                }
            }
            // refill xa with batch g+2
            {
                const int ga = (g + 2) & (K1_NB - 1);
                #pragma unroll
                for (int r = 0; r < K1_RPW; r++)
                    xa[r] = *reinterpret_cast<const float4*>(
                                xw + (long long)r * DIN + 16 * ga);
            }
            // ---- batch g+1 (xb), A frag at bt = 2j+1 ----
            {
                ulonglong2 fa = *reinterpret_cast<const ulonglong2*>(asl + 32 * (2 * j + 1));
                ulonglong2 fb = *reinterpret_cast<const ulonglong2*>(asl + 32 * (2 * j + 1) + 4);
                #pragma unroll
                for (int r = 0; r < K1_RPW; r++) {
                    ffma2(acc[r], pk2(xb[r].x), fa.x);
                    ffma2(acc[r], pk2(xb[r].y), fa.y);
                    ffma2(acc[r], pk2(xb[r].z), fb.x);
                    ffma2(acc[r], pk2(xb[r].w), fb.y);
                }
            }
            // refill xb with batch g+3
            {
                const int gb = (g + 3) & (K1_NB - 1);
                #pragma unroll
                for (int r = 0; r < K1_RPW; r++)
                    xb[r] = *reinterpret_cast<const float4*>(
                                xw + (long long)r * DIN + 16 * gb);
            }
        }

        if (t + 2 < K1_TILES) issueA(t + 2, (t + 2) % K1_NST);
        asm volatile("cp.async.commit_group;");
    }

    // reduce over the 4 k-quarters within each quad
    #pragma unroll
    for (int r = 0; r < K1_RPW; r++) {
        acc[r] = add2(acc[r], __shfl_xor_sync(0xffffffffu, acc[r], 1));
        acc[r] = add2(acc[r], __shfl_xor_sync(0xffffffffu, acc[r], 2));
    }
    if (ksub == 0) {
        #pragma unroll
        for (int r = 0; r < K1_RPW; r++) {
            long long idx = (rowBase + r) * (KSPLIT * RNK) + split * RNK + 2 * rp;
            *reinterpret_cast<unsigned long long*>(&g_t[idx]) = acc[r];
        }
    }
}

// ================= K2: out = (t0 + t1) @ B =================
__global__ void __launch_bounds__(K2_THREADS, 2)
lora_k2(const float* __restrict__ B, float* __restrict__ out)
{
    __shared__ unsigned long long ts2[K2_ROWS][RNK];   // t, packed-dup f32x2

    const int tid = threadIdx.x;
    const long long rowBase = (long long)blockIdx.x * K2_ROWS;

    // load t (both splits), combine, pack duplicated (first 128 threads)
    if (tid < 128) {
        const int row = tid >> 3, j = tid & 7;          // 16 rows x 8 f2-granules
        const float* tp = &g_t[(rowBase + row) * (KSPLIT * RNK) + 2 * j];
        float2 a = *reinterpret_cast<const float2*>(tp);
        float2 b = *reinterpret_cast<const float2*>(tp + RNK);
        ts2[row][2 * j]     = pk2(a.x + b.x);
        ts2[row][2 * j + 1] = pk2(a.y + b.y);
    }
    __syncthreads();

    // 4 passes of 1024 cols; thread owns 4 cols; B reg-cached, reused 16 rows
    #pragma unroll 1
    for (int p = 0; p < 4; p++) {
        const int j = p * 1024 + tid * 4;
        ulonglong2 Breg[RNK];
        #pragma unroll
        for (int r = 0; r < RNK; r++)
            Breg[r] = *reinterpret_cast<const ulonglong2*>(B + (long long)r * DOUT + j);

        #pragma unroll 2
        for (int row = 0; row < K2_ROWS; row++) {
            const ulonglong2* tr = reinterpret_cast<const ulonglong2*>(ts2[row]);
            // 4 independent FFMA2 chains (depth 8) instead of 2 (depth 16)
            unsigned long long aL0 = 0ULL, aH0 = 0ULL, aL1 = 0ULL, aH1 = 0ULL;
            #pragma unroll
            for (int rr = 0; rr < 4; rr++) {
                ulonglong2 tA = tr[rr];          // ranks 2rr, 2rr+1
                ulonglong2 tB = tr[rr + 4];      // ranks 2rr+8, 2rr+9
                ffma2(aL0, tA.x, Breg[2 * rr].x);
                ffma2(aH0, tA.x, Breg[2 * rr].y);
                ffma2(aL0, tA.y, Breg[2 * rr + 1].x);
                ffma2(aH0, tA.y, Breg[2 * rr + 1].y);
                ffma2(aL1, tB.x, Breg[2 * rr + 8].x);
                ffma2(aH1, tB.x, Breg[2 * rr + 8].y);
                ffma2(aL1, tB.y, Breg[2 * rr + 9].x);
                ffma2(aH1, tB.y, Breg[2 * rr + 9].y);
            }
            ulonglong2 o;
            o.x = add2(aL0, aL1);
            o.y = add2(aH0, aH1);
            *reinterpret_cast<ulonglong2*>(
                out + (rowBase + row) * (long long)DOUT + j) = o;
        }
    }
}

extern "C" void kernel_launch(void* const* d_in, const int* in_sizes, int n_in,
                              void* d_out, int out_size) {
    const float* x = (const float*)d_in[0];   // [4, 2048, 4096]
    const float* A = (const float*)d_in[1];   // [4096, 16]
    const float* B = (const float*)d_in[2];   // [16, 4096]
    float* out = (float*)d_out;               // [4, 2048, 4096]

    lora_k1<<<K1_GRID, K1_THREADS>>>(x, A);
    lora_k2<<<K2_GRID, K2_THREADS>>>(B, out);
}

// round 8
// speedup vs baseline: 1.9476x; 1.2671x over previous
#include <cuda_runtime.h>

#define DIN     4096
#define DOUT    4096
#define RNK     16
#define NROWS   8192            // 4*2048

// ---------------- K1 geometry ----------------
#define K1_THREADS 128
#define K1_RPW     8            // rows per warp
#define K1_ROWS    32           // rows per block (4 warps x 8)
#define KSPLIT     4
#define KQ         (DIN / KSPLIT)        // 1024
#define K1_KT      64                    // k per pipeline tile
#define K1_NST     3
#define K1_TILES   (KQ / K1_KT)          // 16
#define AP2        132                   // A rank-pair row pitch (KT*2+4)
#define XS_F       (K1_ROWS * K1_KT)     // 2048 floats x-stage
#define AS_F       (8 * AP2)             // 1056 floats A-stage
#define STG_F      (XS_F + AS_F)         // 3104 floats
#define K1_GRID    (NROWS / K1_ROWS * KSPLIT)   // 1024

// ---------------- K2 geometry ----------------
#define K2_THREADS 128
#define K2_ROWS    16
#define K2_CBLK    8                     // column blocks of 512
#define K2_GRID    ((NROWS / K2_ROWS) * K2_CBLK)   // 4096

// t scratch: [row][split][rank] floats = 2 MB
__device__ float g_t[NROWS * KSPLIT * RNK];

__device__ __forceinline__ unsigned long long pk2(float v) {
    unsigned long long r;
    asm("mov.b64 %0, {%1, %1};" : "=l"(r) : "f"(v));
    return r;
}
__device__ __forceinline__ void ffma2(unsigned long long &acc,
                                      unsigned long long a, unsigned long long b) {
    asm("fma.rn.f32x2 %0, %1, %2, %0;" : "+l"(acc) : "l"(a), "l"(b));
}
__device__ __forceinline__ unsigned long long add2(unsigned long long a,
                                                   unsigned long long b) {
    unsigned long long d;
    asm("add.rn.f32x2 %0, %1, %2;" : "=l"(d) : "l"(a), "l"(b));
    return d;
}
__device__ __forceinline__ unsigned su32(const void* p) {
    unsigned a;
    asm("{ .reg .u64 t; cvta.to.shared.u64 t, %1; cvt.u32.u64 %0, t; }"
        : "=r"(a) : "l"(p));
    return a;
}
__device__ __forceinline__ void cpa16(unsigned d, const void* s) {
    asm volatile("cp.async.cg.shared.global [%0], [%1], 16;" :: "r"(d), "l"(s));
}
__device__ __forceinline__ void cpa8(unsigned d, const void* s) {
    asm volatile("cp.async.ca.shared.global [%0], [%1], 8;" :: "r"(d), "l"(s));
}

// ================= K1: t_partial = x @ A  (split-K x4) =================
__global__ void __launch_bounds__(K1_THREADS, 4)
lora_k1(const float* __restrict__ x, const float* __restrict__ A)
{
    __shared__ float sm[K1_NST * STG_F];     // ~36.4 KB: x + A tiles

    const int tid  = threadIdx.x;
    const int lane = tid & 31;
    const int warp = tid >> 5;
    const int rp   = lane >> 2;              // rank-pair 0..7
    const int ksub = lane & 3;               // k-quarter within a 16-k batch
    const int rb    = blockIdx.x >> 2;
    const int split = blockIdx.x & 3;
    const int k0    = split * KQ;
    const long long rowBase = (long long)rb * K1_ROWS;
    const unsigned  smb = su32(sm);

    // cp.async tile: x [32 rows x 64 k] (16B granules) + A rank-pair major (8B)
    auto issue = [&](int tile, int stg) {
        const unsigned xs = smb + (unsigned)(stg * STG_F) * 4u;
        const unsigned as = xs + XS_F * 4u;
        const long long gk = k0 + tile * K1_KT;
        // x: 512 granules of 16B (32 rows x 16 granules), 4 per thread
        #pragma unroll
        for (int m = 0; m < 4; m++) {
            int g   = tid + m * K1_THREADS;
            int row = g >> 4, c = g & 15;
            cpa16(xs + (unsigned)(row * K1_KT + c * 4) * 4u,
                  x + (rowBase + row) * DIN + gk + c * 4);
        }
        // A: 512 granules of 8B (64 k x 8 rank-pairs), 4 per thread
        const float* Ag = A + gk * RNK;
        #pragma unroll
        for (int m = 0; m < 4; m++) {
            int g = tid + m * K1_THREADS;
            int k = g >> 3, r8 = g & 7;
            cpa8(as + (unsigned)(r8 * AP2 + 2 * k) * 4u, Ag + k * RNK + 2 * r8);
        }
    };

    issue(0, 0); asm volatile("cp.async.commit_group;");
    issue(1, 1); asm volatile("cp.async.commit_group;");

    unsigned long long acc[K1_RPW];
    #pragma unroll
    for (int r = 0; r < K1_RPW; r++) acc[r] = 0ULL;

    #pragma unroll 1
    for (int t = 0; t < K1_TILES; t++) {
        asm volatile("cp.async.wait_group %0;" :: "n"(1));
        __syncthreads();

        const float* xs  = sm + (t % K1_NST) * STG_F;
        const float* asl = xs + XS_F + rp * AP2 + 8 * ksub;
        const float* xp  = xs + (warp * K1_RPW) * K1_KT + 4 * ksub;

        #pragma unroll
        for (int b = 0; b < K1_KT / 16; b++) {       // 4 batches of 16 k
            ulonglong2 fa = *reinterpret_cast<const ulonglong2*>(asl + 32 * b);
            ulonglong2 fb = *reinterpret_cast<const ulonglong2*>(asl + 32 * b + 4);

            #pragma unroll
            for (int r = 0; r < K1_RPW; r++) {
                float4 xv = *reinterpret_cast<const float4*>(
                                xp + r * K1_KT + 16 * b);
                ffma2(acc[r], pk2(xv.x), fa.x);
                ffma2(acc[r], pk2(xv.y), fa.y);
                ffma2(acc[r], pk2(xv.z), fb.x);
                ffma2(acc[r], pk2(xv.w), fb.y);
            }
        }

        __syncthreads();                              // all done with stage t
        if (t + 2 < K1_TILES) issue(t + 2, (t + 2) % K1_NST);
        asm volatile("cp.async.commit_group;");
    }

    // reduce over the 4 k-quarters within each quad
    #pragma unroll
    for (int r = 0; r < K1_RPW; r++) {
        acc[r] = add2(acc[r], __shfl_xor_sync(0xffffffffu, acc[r], 1));
        acc[r] = add2(acc[r], __shfl_xor_sync(0xffffffffu, acc[r], 2));
    }
    if (ksub == 0) {
        #pragma unroll
        for (int r = 0; r < K1_RPW; r++) {
            long long row = rowBase + warp * K1_RPW + r;
            long long idx = row * (KSPLIT * RNK) + split * RNK + 2 * rp;
            *reinterpret_cast<unsigned long long*>(&g_t[idx]) = acc[r];
        }
    }
}

// ================= K2: out = (sum_s t_s) @ B  (row x col 2D grid) ============
__global__ void __launch_bounds__(K2_THREADS, 5)
lora_k2(const float* __restrict__ B, float* __restrict__ out)
{
    __shared__ unsigned long long ts2[K2_ROWS][RNK];   // t, packed-dup f32x2

    const int tid = threadIdx.x;
    const int cb  = blockIdx.x & (K2_CBLK - 1);        // column block (512 cols)
    const long long rowBase = (long long)(blockIdx.x >> 3) * K2_ROWS;
    const int j = cb * 512 + tid * 4;

    // load t (4 splits), combine, pack duplicated: 128 units = 16 rows x 8 rp
    {
        const int row = tid >> 3, q = tid & 7;
        const float* tp = &g_t[(rowBase + row) * (KSPLIT * RNK) + 2 * q];
        float2 s0 = *reinterpret_cast<const float2*>(tp);
        float2 s1 = *reinterpret_cast<const float2*>(tp + RNK);
        float2 s2 = *reinterpret_cast<const float2*>(tp + 2 * RNK);
        float2 s3 = *reinterpret_cast<const float2*>(tp + 3 * RNK);
        ts2[row][2 * q]     = pk2((s0.x + s1.x) + (s2.x + s3.x));
        ts2[row][2 * q + 1] = pk2((s0.y + s1.y) + (s2.y + s3.y));
    }

    // B columns for this thread: 16 ranks x 4 cols, cached in registers
    ulonglong2 Breg[RNK];
    #pragma unroll
    for (int r = 0; r < RNK; r++)
        Breg[r] = *reinterpret_cast<const ulonglong2*>(B + (long long)r * DOUT + j);

    __syncthreads();

    #pragma unroll 2
    for (int row = 0; row < K2_ROWS; row++) {
        const ulonglong2* tr = reinterpret_cast<const ulonglong2*>(ts2[row]);
        unsigned long long aL0 = 0ULL, aH0 = 0ULL, aL1 = 0ULL, aH1 = 0ULL;
        #pragma unroll
        for (int rr = 0; rr < 4; rr++) {
            ulonglong2 tA = tr[rr];          // ranks 2rr, 2rr+1 (dup-packed)
            ulonglong2 tB = tr[rr + 4];      // ranks 2rr+8, 2rr+9
            ffma2(aL0, tA.x, Breg[2 * rr].x);
            ffma2(aH0, tA.x, Breg[2 * rr].y);
            ffma2(aL0, tA.y, Breg[2 * rr + 1].x);
            ffma2(aH0, tA.y, Breg[2 * rr + 1].y);
            ffma2(aL1, tB.x, Breg[2 * rr + 8].x);
            ffma2(aH1, tB.x, Breg[2 * rr + 8].y);
            ffma2(aL1, tB.y, Breg[2 * rr + 9].x);
            ffma2(aH1, tB.y, Breg[2 * rr + 9].y);
        }
        ulonglong2 o;
        o.x = add2(aL0, aL1);
        o.y = add2(aH0, aH1);
        *reinterpret_cast<ulonglong2*>(
            out + (rowBase + row) * (long long)DOUT + j) = o;
    }
}

extern "C" void kernel_launch(void* const* d_in, const int* in_sizes, int n_in,
                              void* d_out, int out_size) {
    const float* x = (const float*)d_in[0];   // [4, 2048, 4096]
    const float* A = (const float*)d_in[1];   // [4096, 16]
    const float* B = (const float*)d_in[2];   // [16, 4096]
    float* out = (float*)d_out;               // [4, 2048, 4096]

    lora_k1<<<K1_GRID, K1_THREADS>>>(x, A);
    lora_k2<<<K2_GRID, K2_THREADS>>>(B, out);
}